// round 16
// baseline (speedup 1.0000x reference)
#include <cuda_runtime.h>
#include <cuda_bf16.h>

#define B_ 8
#define N_ 4096
#define KNN 20
#define PTS (B_*N_)
#define FULLMASK 0xFFFFFFFFu
typedef unsigned long long ull;

// ---------------- static device scratch (no allocation) ----------------
__device__ float2   g_xp[3*PTS];
__device__ float    g_xx[PTS];
__device__ float    g_nb[PTS*64];
__device__ float    g_cc[PTS*64];
__device__ int      g_idx[PTS*KNN];
__device__ float    g_m2[PTS*128];
__device__ float    g_s[2432];       // s1[64] ss1[64] s2[128] ss2[128] s3[1024] ss3[1024]
__device__ float    g_ab[384];       // a1[64] b1[64] a2[128] b2[128]
__device__ unsigned g_z3e[B_*1024];
__device__ float    g_g[B_*1024];
__device__ float    g_g4[B_*512];
__device__ float    g_mat[B_*9];
__device__ float    g_bias[B_*3];
__device__ int      g_c0 = 0;
__device__ int      g_c1 = 0;
__device__ int      g_c2 = 0;
// conv2 weights (R8 layout)
__device__ ulonglong2 g_w2t[32][64];       // [j2][cp]
// conv3 weights: row-major bf16 hi/lo images [1024][128]
__device__ unsigned short g_w3hb[131072];
__device__ unsigned short g_w3lb[131072];

__device__ __forceinline__ float lrelu(float x){ return x >= 0.f ? x : 0.2f*x; }
__device__ __forceinline__ unsigned fenc(float f){
    unsigned u = __float_as_uint(f);
    return (u & 0x80000000u) ? ~u : (u | 0x80000000u);
}
__device__ __forceinline__ float fdec(unsigned u){
    u = (u & 0x80000000u) ? (u & 0x7FFFFFFFu) : ~u;
    return __uint_as_float(u);
}
__device__ __forceinline__ float f2lo(ull v){ return __uint_as_float((unsigned)v); }
__device__ __forceinline__ float f2hi(ull v){ return __uint_as_float((unsigned)(v>>32)); }
__device__ __forceinline__ void ffma2(ull& d, ull a, ull b){
    asm("fma.rn.f32x2 %0, %1, %2, %0;" : "+l"(d) : "l"(a), "l"(b));
}
__device__ __forceinline__ void fadd2(ull& d, ull b){
    asm("add.rn.f32x2 %0, %0, %1;" : "+l"(d) : "l"(b));
}
// mma.sync bf16 m16n8k16 (base sm_80+ ISA; works at target sm_103)
__device__ __forceinline__ void mma16816(float* c,
        unsigned a0, unsigned a1, unsigned a2, unsigned a3,
        unsigned b0, unsigned b1){
    asm volatile("mma.sync.aligned.m16n8k16.row.col.f32.bf16.bf16.f32 "
        "{%0,%1,%2,%3}, {%4,%5,%6,%7}, {%8,%9}, {%0,%1,%2,%3};"
        : "+f"(c[0]), "+f"(c[1]), "+f"(c[2]), "+f"(c[3])
        : "r"(a0), "r"(a1), "r"(a2), "r"(a3), "r"(b0), "r"(b1));
}

// ---------------- kernel 0: zero + SoA + norms + conv1 precompute + W layouts ----
__global__ void k_prep(const float* __restrict__ x, const float* __restrict__ w1,
                       const float* __restrict__ w2, const float* __restrict__ w3){
    __shared__ float wa[384], wd[384];
    int t = threadIdx.x;
    if (blockIdx.x == 0){
        for (int i = t; i < 2432; i += 256) g_s[i] = 0.f;
        for (int i = t; i < B_*1024; i += 256) g_z3e[i] = 0u;
    }
    for (int i = t; i < 384; i += 256){
        int o = i/6, c = i%6;
        float a = w1[o*12 + c];
        wa[i] = a;
        wd[i] = w1[o*12 + 6 + c] - a;
    }
    __syncthreads();

    int p = blockIdx.x*256 + t;            // 128 blocks x 256 = 32768
    // W3 hi/lo bf16 images (row-major): 4 entries per thread
    #pragma unroll
    for (int e = 0; e < 4; e++){
        int idx = p + e*32768;             // 0..131071
        float v = w3[idx];
        __nv_bfloat16 h = __float2bfloat16(v);
        float res = v - __bfloat162float(h);
        __nv_bfloat16 l = __float2bfloat16(res);
        g_w3hb[idx] = *(unsigned short*)&h;
        g_w3lb[idx] = *(unsigned short*)&l;
    }
    // W2 transpose
    if (p < 2048){
        int j2 = p >> 6, cp = p & 63;
        int row = 2*cp + (j2 >= 16 ? 1 : 0);
        int j = j2 & 15;
        g_w2t[j2][cp] = ((const ulonglong2*)(w2 + row*64))[j];
    }
    {
        int b = p >> 12, n = p & 4095;
        const float* xb = x + b*6*N_ + n;
        float x0=xb[0], x1=xb[N_], x2=xb[2*N_], x3=xb[3*N_], x4=xb[4*N_], x5=xb[5*N_];
        g_xp[p]       = make_float2(x0,x1);
        g_xp[PTS+p]   = make_float2(x2,x3);
        g_xp[2*PTS+p] = make_float2(x4,x5);
        g_xx[p] = x0*x0+x1*x1+x2*x2+x3*x3+x4*x4+x5*x5;
    }
    int o = t & 63;
    int pbase = blockIdx.x*256;
    for (int pi = (t>>6); pi < 256; pi += 4){
        int pp = pbase + pi;
        int bb = pp >> 12, nn = pp & 4095;
        const float* xp = x + bb*6*N_ + nn;
        float y0=xp[0], y1=xp[N_], y2=xp[2*N_], y3=xp[3*N_], y4=xp[4*N_], y5=xp[5*N_];
        const float* A = wa + o*6;
        const float* D = wd + o*6;
        g_nb[pp*64+o] = y0*A[0]+y1*A[1]+y2*A[2]+y3*A[3]+y4*A[4]+y5*A[5];
        g_cc[pp*64+o] = y0*D[0]+y1*D[1]+y2*D[2]+y3*D[3]+y4*D[4]+y5*D[5];
    }
}

// ---------------- kernel 1: KNN top-20 (4 queries/warp, short insert chain) -------
__global__ void __launch_bounds__(512) k_knn(){
    int b   = blockIdx.x >> 6;
    int sec = blockIdx.x & 63;
    int w    = threadIdx.x >> 5;
    int lane = threadIdx.x & 31;
    int base = b*N_;
    const float2* xp0 = g_xp + base;
    const float2* xp1 = g_xp + PTS + base;
    const float2* xp2 = g_xp + 2*PTS + base;
    const float*  xxp = g_xx + base;

    int n0 = sec*64 + w*4;
    float q[4][6]; float lv[4]; int li[4]; float minv[4];
    #pragma unroll
    for (int j=0;j<4;j++){
        float2 a = xp0[n0+j], c = xp1[n0+j], e = xp2[n0+j];
        q[j][0]=a.x; q[j][1]=a.y; q[j][2]=c.x; q[j][3]=c.y; q[j][4]=e.x; q[j][5]=e.y;
        lv[j] = -3.4e38f; li[j] = 0; minv[j] = -3.4e38f;
    }

    for (int mb = 0; mb < N_; mb += 32){
        int m = mb + lane;
        float2 a = xp0[m], c = xp1[m], e = xp2[m];
        float xxm = xxp[m];
        float v[4];
        #pragma unroll
        for (int j=0;j<4;j++){
            float d = q[j][0]*a.x + q[j][1]*a.y + q[j][2]*c.x
                    + q[j][3]*c.y + q[j][4]*e.x + q[j][5]*e.y;
            v[j] = 2.f*d - xxm;
        }
        #pragma unroll
        for (int j=0;j<4;j++){
            unsigned cand = __ballot_sync(FULLMASK, v[j] > minv[j]);
            bool any = (cand != 0u);
            while (cand){
                int src = __ffs(cand)-1; cand &= cand-1;
                float cv = __shfl_sync(FULLMASK, v[j], src);
                float pv = __shfl_up_sync(FULLMASK, lv[j], 1);
                int   pq = __shfl_up_sync(FULLMASK, li[j], 1);
                unsigned lt = __ballot_sync(FULLMASK, lv[j] < cv) & 0xFFFFFu;
                if (lt){
                    int pos = __ffs(lt)-1;
                    if (lane > pos && lane < KNN){ lv[j]=pv; li[j]=pq; }
                    if (lane == pos)             { lv[j]=cv; li[j]=mb+src; }
                }
            }
            if (any) minv[j] = __shfl_sync(FULLMASK, lv[j], 19);
        }
    }
    #pragma unroll
    for (int j=0;j<4;j++)
        if (lane < KNN) g_idx[(base + n0 + j)*KNN + lane] = li[j];
}

// ---------------- kernel 2: z1 channel stats + bn1 finalize (last block) ----------------
__global__ void __launch_bounds__(256) k_stats1(const float* __restrict__ ga,
                                                const float* __restrict__ be){
    int t = threadIdx.x, o = t & 63, grp = t >> 6;
    float s = 0.f, ss = 0.f;
    for (int pi = blockIdx.x*4 + grp; pi < PTS; pi += 4096){
        float ccv = g_cc[pi*64 + o];
        int bbase = (pi >> 12) << 12;
        const int* ip = g_idx + pi*KNN;
        #pragma unroll
        for (int k=0;k<KNN;k++){
            int r = ip[k];
            float v = g_nb[(bbase + r)*64 + o] + ccv;
            s += v; ss += v*v;
        }
    }
    __shared__ float sh[256], sh2[256];
    sh[t] = s; sh2[t] = ss;
    __syncthreads();
    if (t < 64){
        atomicAdd(&g_s[t],    sh[t]+sh[t+64]+sh[t+128]+sh[t+192]);
        atomicAdd(&g_s[64+t], sh2[t]+sh2[t+64]+sh2[t+128]+sh2[t+192]);
    }
    __threadfence();
    __syncthreads();
    __shared__ int lastb;
    if (t == 0) lastb = (atomicAdd(&g_c0, 1) == (int)gridDim.x - 1);
    __syncthreads();
    if (lastb){
        if (t < 64){
            float cnt = (float)(PTS*KNN);
            float m = g_s[t]/cnt;
            float var = g_s[64+t]/cnt - m*m;
            float a = ga[t]*rsqrtf(var + 1e-5f);
            g_ab[t]    = a;
            g_ab[64+t] = be[t] - m*a;
        }
        if (t == 0) g_c0 = 0;
    }
}

// ---------------- kernel 3: conv2, persistent (R8, measured ~320us) ----------------
#define C2_TILES 2048
__global__ void __launch_bounds__(128) k_conv2(const float* __restrict__ ga,
                                               const float* __restrict__ be){
    int t = threadIdx.x;
    int kh = t >> 6;
    int cp = t & 63;
    ull w0[32], w1[32];
    #pragma unroll
    for (int j=0;j<16;j++){
        ulonglong2 v0 = g_w2t[j][cp];    w0[2*j]=v0.x; w0[2*j+1]=v0.y;
        ulonglong2 v1 = g_w2t[16+j][cp]; w1[2*j]=v1.x; w1[2*j+1]=v1.y;
    }
    __shared__ __align__(16) float h1[4][20*64];
    __shared__ float mx[2][4][128];
    float a1 = g_ab[cp], b1 = g_ab[64+cp];
    float s0=0.f, ss0=0.f, s1=0.f, ss1=0.f;

    for (int tile = blockIdx.x; tile < C2_TILES; tile += gridDim.x){
        int p0 = tile*16;
        for (int ph = 0; ph < 4; ++ph){
            int pb = p0 + ph*4;
            __syncthreads();
            if (ph > 0 && kh == 0){
                #pragma unroll
                for (int pp=0;pp<4;pp++){
                    int pi = pb - 4 + pp;
                    float2 v;
                    v.x = fmaxf(mx[0][pp][2*cp],   mx[1][pp][2*cp]);
                    v.y = fmaxf(mx[0][pp][2*cp+1], mx[1][pp][2*cp+1]);
                    *(float2*)(g_m2 + pi*128 + 2*cp) = v;
                }
            }
            #pragma unroll
            for (int pp=0;pp<4;pp++){
                int pi = pb + pp;
                int bbase = (pi >> 12) << 12;
                float ccv = g_cc[pi*64 + cp];
                const int* ip = g_idx + pi*KNN;
                #pragma unroll
                for (int kk=0;kk<10;kk++){
                    int k = kh*10 + kk;
                    int r = ip[k];
                    h1[pp][k*64 + cp] = lrelu(fmaf(a1, g_nb[(bbase + r)*64 + cp] + ccv, b1));
                }
            }
            __syncthreads();
            #pragma unroll
            for (int pp=0;pp<4;pp++){
                float m0 = -3.4e38f, m1 = -3.4e38f;
                for (int kk=0;kk<10;kk++){
                    int k = kh*10 + kk;
                    const ulonglong2* hp = (const ulonglong2*)(h1[pp] + k*64);
                    ull A0=0ull, B0=0ull, A1=0ull, B1=0ull;
                    #pragma unroll
                    for (int j=0;j<16;j++){
                        ulonglong2 h = hp[j];
                        ffma2(A0, w0[2*j],   h.x);
                        ffma2(B0, w0[2*j+1], h.y);
                        ffma2(A1, w1[2*j],   h.x);
                        ffma2(B1, w1[2*j+1], h.y);
                    }
                    fadd2(A0, B0); fadd2(A1, B1);
                    float z0 = f2lo(A0) + f2hi(A0);
                    float z1 = f2lo(A1) + f2hi(A1);
                    s0 += z0; ss0 += z0*z0; m0 = fmaxf(m0, z0);
                    s1 += z1; ss1 += z1*z1; m1 = fmaxf(m1, z1);
                }
                mx[kh][pp][2*cp]   = m0;
                mx[kh][pp][2*cp+1] = m1;
            }
        }
        __syncthreads();
        if (kh == 0){
            #pragma unroll
            for (int pp=0;pp<4;pp++){
                int pi = p0 + 12 + pp;
                float2 v;
                v.x = fmaxf(mx[0][pp][2*cp],   mx[1][pp][2*cp]);
                v.y = fmaxf(mx[0][pp][2*cp+1], mx[1][pp][2*cp+1]);
                *(float2*)(g_m2 + pi*128 + 2*cp) = v;
            }
        }
    }
    atomicAdd(&g_s[128+2*cp],   s0);
    atomicAdd(&g_s[128+2*cp+1], s1);
    atomicAdd(&g_s[256+2*cp],   ss0);
    atomicAdd(&g_s[256+2*cp+1], ss1);
    __threadfence();
    __syncthreads();
    __shared__ int lastb;
    if (t == 0) lastb = (atomicAdd(&g_c1, 1) == (int)gridDim.x - 1);
    __syncthreads();
    if (lastb){
        float cnt = (float)(PTS*KNN);
        float m = g_s[128+t]/cnt;
        float var = g_s[256+t]/cnt - m*m;
        float a = ga[t]*rsqrtf(var + 1e-5f);
        g_ab[128+t] = a;
        g_ab[256+t] = be[t] - m*a;
        if (t == 0) g_c1 = 0;
    }
}

// ---------------- kernel 4: conv3 via mma.sync bf16 hi/lo ------------------------
// 512 blocks x 128 thr. Tile = 64 pts. A hi/lo + B chunk-half hi/lo in dynamic smem,
// padded row stride 136 halves (bank-conflict-free fragment loads).
// Warp w: rows w*16..w*16+15 (one m16 tile); 8 n-tiles of 8 ch; 8 k-steps; 3 passes.
#define ROWP 136
__global__ void __launch_bounds__(128) k_conv3m(const float* __restrict__ ga,
                                                const float* __restrict__ be){
    extern __shared__ __align__(16) unsigned short dsm[];
    unsigned short* sAh = dsm;                 // 64*136
    unsigned short* sAl = sAh + 64*ROWP;
    unsigned short* sBh = sAl + 64*ROWP;
    unsigned short* sBl = sBh + 64*ROWP;
    __shared__ float sab[128], sbb[128];
    __shared__ float srS[4][64], srQ[4][64], srM[4][64];

    int t = threadIdx.x, wid = t >> 5, lane = t & 31;
    int g = lane >> 2, tig = lane & 3;
    sab[t] = g_ab[128+t]; sbb[t] = g_ab[256+t];
    __syncthreads();

    int pbase = blockIdx.x*64;
    int bb = blockIdx.x >> 6;
    // ---- A convert: row = t>>1, seg = t&1 (64 cols) ----
    {
        int row = t >> 1, seg = t & 1;
        const float4* src = (const float4*)(g_m2 + (size_t)(pbase+row)*128 + seg*64);
        unsigned short* dh = sAh + row*ROWP + seg*64;
        unsigned short* dl = sAl + row*ROWP + seg*64;
        #pragma unroll
        for (int i=0;i<16;i++){
            float4 v = src[i];
            int c = seg*64 + i*4;
            float z0 = lrelu(fmaf(sab[c],   v.x, sbb[c]));
            float z1 = lrelu(fmaf(sab[c+1], v.y, sbb[c+1]));
            float z2 = lrelu(fmaf(sab[c+2], v.z, sbb[c+2]));
            float z3 = lrelu(fmaf(sab[c+3], v.w, sbb[c+3]));
            __nv_bfloat16 h0=__float2bfloat16(z0), h1=__float2bfloat16(z1),
                          h2=__float2bfloat16(z2), h3=__float2bfloat16(z3);
            __nv_bfloat16 l0=__float2bfloat16(z0-__bfloat162float(h0));
            __nv_bfloat16 l1=__float2bfloat16(z1-__bfloat162float(h1));
            __nv_bfloat16 l2=__float2bfloat16(z2-__bfloat162float(h2));
            __nv_bfloat16 l3=__float2bfloat16(z3-__bfloat162float(h3));
            dh[i*4+0]=*(unsigned short*)&h0; dh[i*4+1]=*(unsigned short*)&h1;
            dh[i*4+2]=*(unsigned short*)&h2; dh[i*4+3]=*(unsigned short*)&h3;
            dl[i*4+0]=*(unsigned short*)&l0; dl[i*4+1]=*(unsigned short*)&l1;
            dl[i*4+2]=*(unsigned short*)&l2; dl[i*4+3]=*(unsigned short*)&l3;
        }
    }

    for (int chunk = 0; chunk < 8; chunk++){
        for (int hf = 0; hf < 2; hf++){
            int ch0 = chunk*128 + hf*64;
            __syncthreads();            // prior use of sB / srX done
            // stage B chunk-half (64 rows x 128 halves), hi and lo
            {
                int row = t >> 1, seg = t & 1;
                const uint4* sh_ = (const uint4*)(g_w3hb + (size_t)(ch0+row)*128 + seg*64);
                const uint4* sl_ = (const uint4*)(g_w3lb + (size_t)(ch0+row)*128 + seg*64);
                uint4* dh = (uint4*)(sBh + row*ROWP + seg*64);
                uint4* dl = (uint4*)(sBl + row*ROWP + seg*64);
                #pragma unroll
                for (int i=0;i<8;i++){ dh[i] = sh_[i]; dl[i] = sl_[i]; }
            }
            __syncthreads();
            float acc[8][4];
            #pragma unroll
            for (int nt=0;nt<8;nt++){ acc[nt][0]=0.f; acc[nt][1]=0.f; acc[nt][2]=0.f; acc[nt][3]=0.f; }
            #pragma unroll 2
            for (int ks = 0; ks < 8; ks++){
                int rA0 = (wid*16 + g)*ROWP + ks*16 + tig*2;
                int rA8 = rA0 + 8*ROWP;
                unsigned ah0 = *(const unsigned*)(sAh + rA0);
                unsigned ah1 = *(const unsigned*)(sAh + rA8);
                unsigned ah2 = *(const unsigned*)(sAh + rA0 + 8);
                unsigned ah3 = *(const unsigned*)(sAh + rA8 + 8);
                unsigned al0 = *(const unsigned*)(sAl + rA0);
                unsigned al1 = *(const unsigned*)(sAl + rA8);
                unsigned al2 = *(const unsigned*)(sAl + rA0 + 8);
                unsigned al3 = *(const unsigned*)(sAl + rA8 + 8);
                #pragma unroll
                for (int nt = 0; nt < 8; nt++){
                    int rB = (nt*8 + g)*ROWP + ks*16 + tig*2;
                    unsigned bh0 = *(const unsigned*)(sBh + rB);
                    unsigned bh1 = *(const unsigned*)(sBh + rB + 8);
                    unsigned bl0 = *(const unsigned*)(sBl + rB);
                    unsigned bl1 = *(const unsigned*)(sBl + rB + 8);
                    mma16816(acc[nt], ah0,ah1,ah2,ah3, bh0,bh1);
                    mma16816(acc[nt], al0,al1,al2,al3, bh0,bh1);
                    mma16816(acc[nt], ah0,ah1,ah2,ah3, bl0,bl1);
                }
            }
            // ---- epilogue: column stats over this warp's 16 rows ----
            #pragma unroll
            for (int nt=0;nt<8;nt++){
                float sE = acc[nt][0] + acc[nt][2];
                float sO = acc[nt][1] + acc[nt][3];
                float qE = acc[nt][0]*acc[nt][0] + acc[nt][2]*acc[nt][2];
                float qO = acc[nt][1]*acc[nt][1] + acc[nt][3]*acc[nt][3];
                float mE = fmaxf(acc[nt][0], acc[nt][2]);
                float mO = fmaxf(acc[nt][1], acc[nt][3]);
                #pragma unroll
                for (int off=4; off<32; off<<=1){
                    sE += __shfl_xor_sync(FULLMASK, sE, off);
                    sO += __shfl_xor_sync(FULLMASK, sO, off);
                    qE += __shfl_xor_sync(FULLMASK, qE, off);
                    qO += __shfl_xor_sync(FULLMASK, qO, off);
                    mE = fmaxf(mE, __shfl_xor_sync(FULLMASK, mE, off));
                    mO = fmaxf(mO, __shfl_xor_sync(FULLMASK, mO, off));
                }
                if (g == 0){
                    int cb = nt*8 + tig*2;
                    srS[wid][cb] = sE; srS[wid][cb+1] = sO;
                    srQ[wid][cb] = qE; srQ[wid][cb+1] = qO;
                    srM[wid][cb] = mE; srM[wid][cb+1] = mO;
                }
            }
            __syncthreads();
            if (t < 64){
                float S = srS[0][t]+srS[1][t]+srS[2][t]+srS[3][t];
                float Q = srQ[0][t]+srQ[1][t]+srQ[2][t]+srQ[3][t];
                float M = fmaxf(fmaxf(srM[0][t], srM[1][t]), fmaxf(srM[2][t], srM[3][t]));
                int ch = ch0 + t;
                atomicAdd(&g_s[384+ch],  S);
                atomicAdd(&g_s[1408+ch], Q);
                atomicMax(&g_z3e[bb*1024 + ch], fenc(M));
            }
        }
    }
    __threadfence();
    __syncthreads();
    __shared__ int lastb;
    if (t == 0) lastb = (atomicAdd(&g_c2, 1) == (int)gridDim.x - 1);
    __syncthreads();
    if (lastb){
        float cnt = (float)PTS;
        for (int c = t; c < 1024; c += 128){
            float m = g_s[384+c]/cnt;
            float var = g_s[1408+c]/cnt - m*m;
            float a = ga[c]*rsqrtf(var + 1e-5f);
            float bo = be[c] - m*a;
            #pragma unroll
            for (int b=0;b<B_;b++)
                g_g[b*1024+c] = lrelu(fmaf(a, fdec(g_z3e[b*1024+c]), bo));
        }
        if (t == 0) g_c2 = 0;
    }
}

// ---------------- kernel 5: fc1 + bn4 + lrelu ----------------
__global__ void __launch_bounds__(128) k_fc1(const float* __restrict__ fw,
                                             const float* __restrict__ g4g,
                                             const float* __restrict__ g4b){
    __shared__ float gs[B_*1024];
    int t = threadIdx.x;
    for (int i=t;i<B_*1024;i+=128) gs[i] = g_g[i];
    __syncthreads();
    int w = t >> 5, lane = t & 31;
    for (int jj=0;jj<2;jj++){
        int j = blockIdx.x*8 + w*2 + jj;
        const float* wrow = fw + j*1024;
        float acc[8] = {0,0,0,0,0,0,0,0};
        for (int c=lane;c<1024;c+=32){
            float wv = wrow[c];
            #pragma unroll
            for (int b=0;b<8;b++) acc[b] += gs[b*1024+c]*wv;
        }
        #pragma unroll
        for (int b=0;b<8;b++){
            #pragma unroll
            for (int off=16;off;off>>=1) acc[b] += __shfl_xor_sync(FULLMASK, acc[b], off);
        }
        if (lane == 0){
            float m=0.f;
            #pragma unroll
            for (int b=0;b<8;b++) m += acc[b];
            m *= 0.125f;
            float var=0.f;
            #pragma unroll
            for (int b=0;b<8;b++){ float d = acc[b]-m; var += d*d; }
            var *= 0.125f;
            float a = g4g[j]*rsqrtf(var + 1e-5f);
            float bo = g4b[j] - m*a;
            #pragma unroll
            for (int b=0;b<8;b++) g_g4[b*512+j] = lrelu(a*acc[b] + bo);
        }
    }
}

// ---------------- kernel 6: fc2+bn5+lrelu, fc3/fc4 -> mat/bias ----------------
__global__ void __launch_bounds__(256) k_head(const float* __restrict__ f2w,
        const float* __restrict__ g5g, const float* __restrict__ g5b,
        const float* __restrict__ f3w, const float* __restrict__ f3b,
        const float* __restrict__ f4w, const float* __restrict__ f4b){
    __shared__ float g4s[B_*512];
    __shared__ float g5s[B_*256];
    int t = threadIdx.x, w = t >> 5, lane = t & 31;
    for (int i=t;i<B_*512;i+=256) g4s[i] = g_g4[i];
    __syncthreads();
    for (int jj=0;jj<32;jj++){
        int j = w*32 + jj;
        const float* wrow = f2w + j*512;
        float acc[8] = {0,0,0,0,0,0,0,0};
        for (int c=lane;c<512;c+=32){
            float wv = wrow[c];
            #pragma unroll
            for (int b=0;b<8;b++) acc[b] += g4s[b*512+c]*wv;
        }
        #pragma unroll
        for (int b=0;b<8;b++){
            #pragma unroll
            for (int off=16;off;off>>=1) acc[b] += __shfl_xor_sync(FULLMASK, acc[b], off);
        }
        if (lane == 0){
            float m=0.f;
            #pragma unroll
            for (int b=0;b<8;b++) m += acc[b];
            m *= 0.125f;
            float var=0.f;
            #pragma unroll
            for (int b=0;b<8;b++){ float d = acc[b]-m; var += d*d; }
            var *= 0.125f;
            float a = g5g[j]*rsqrtf(var + 1e-5f);
            float bo = g5b[j] - m*a;
            #pragma unroll
            for (int b=0;b<8;b++) g5s[b*256+j] = lrelu(a*acc[b] + bo);
        }
    }
    __syncthreads();
    for (int i=0;i<12;i++){
        int task = w*12 + i;
        int b = task / 12, jo = task % 12;
        const float* wrow = (jo < 9) ? (f3w + jo*256) : (f4w + (jo-9)*256);
        float acc = 0.f;
        for (int c=lane;c<256;c+=32) acc += g5s[b*256+c]*wrow[c];
        #pragma unroll
        for (int off=16;off;off>>=1) acc += __shfl_xor_sync(FULLMASK, acc, off);
        if (lane == 0){
            if (jo < 9){
                int r = jo/3, cc = jo%3;
                g_mat[b*9+jo] = acc + f3b[jo] + (r==cc ? 1.f : 0.f);
            } else {
                g_bias[b*3 + (jo-9)] = acc + f4b[jo-9];
            }
        }
    }
}

// ---------------- kernel 7: apply 3x3 transform ----------------
__global__ void k_out(const float* __restrict__ x, float* __restrict__ out){
    int p = blockIdx.x*1024 + threadIdx.x;
    int b = p >> 12, n = p & 4095;
    const float* xb = x + b*6*N_ + n;
    float x0 = xb[0], x1 = xb[N_], x2 = xb[2*N_];
    const float* M  = g_mat + b*9;
    const float* Bi = g_bias + b*3;
    float* ob = out + b*3*N_ + n;
    ob[0]    = x0*M[0] + x1*M[3] + x2*M[6] + Bi[0];
    ob[N_]   = x0*M[1] + x1*M[4] + x2*M[7] + Bi[1];
    ob[2*N_] = x0*M[2] + x1*M[5] + x2*M[8] + Bi[2];
}

// ---------------- launch ----------------
extern "C" void kernel_launch(void* const* d_in, const int* in_sizes, int n_in,
                              void* d_out, int out_size){
    const float* x     = (const float*)d_in[0];
    const float* w1    = (const float*)d_in[1];
    const float* bn1g  = (const float*)d_in[2];
    const float* bn1b  = (const float*)d_in[3];
    const float* w2    = (const float*)d_in[4];
    const float* bn2g  = (const float*)d_in[5];
    const float* bn2b  = (const float*)d_in[6];
    const float* w3    = (const float*)d_in[7];
    const float* bn3g  = (const float*)d_in[8];
    const float* bn3b  = (const float*)d_in[9];
    const float* fc1w  = (const float*)d_in[10];
    const float* bn4g  = (const float*)d_in[11];
    const float* bn4b  = (const float*)d_in[12];
    const float* fc2w  = (const float*)d_in[13];
    const float* bn5g  = (const float*)d_in[14];
    const float* bn5b  = (const float*)d_in[15];
    const float* fc3w  = (const float*)d_in[16];
    const float* fc3b  = (const float*)d_in[17];
    const float* fc4w  = (const float*)d_in[18];
    const float* fc4b  = (const float*)d_in[19];
    float* out = (float*)d_out;

    static int smem_set = 0;
    int c3smem = 4*64*ROWP*2;              // 69632 B dynamic
    if (!smem_set){
        cudaFuncSetAttribute(k_conv3m, cudaFuncAttributeMaxDynamicSharedMemorySize, c3smem);
        smem_set = 1;
    }

    k_prep  <<<128, 256>>>(x, w1, w2, w3);       // 1
    k_knn   <<<B_*64, 512>>>();                  // 2
    k_stats1<<<1024, 256>>>(bn1g, bn1b);         // 3
    k_conv2 <<<444, 128>>>(bn2g, bn2b);          // 4  <- ncu capture slot
    k_conv3m<<<512, 128, c3smem>>>(bn3g, bn3b);  // 5  <- HMMA conv3
    k_fc1   <<<64, 128>>>(fc1w, bn4g, bn4b);
    k_head  <<<1, 256>>>(fc2w, bn5g, bn5b, fc3w, fc3b, fc4w, fc4b);
    k_out   <<<32, 1024>>>(x, out);
}

// round 17
// speedup vs baseline: 1.0239x; 1.0239x over previous
#include <cuda_runtime.h>

#define B_ 8
#define N_ 4096
#define KNN 20
#define PTS (B_*N_)
#define FULLMASK 0xFFFFFFFFu
typedef unsigned long long ull;

// ---------------- static device scratch (no allocation) ----------------
__device__ float2   g_xp[3*PTS];
__device__ float    g_xx[PTS];
__device__ float    g_nb[PTS*64];
__device__ float    g_cc[PTS*64];
__device__ int      g_idx[PTS*KNN];
__device__ float    g_m2[PTS*128];
__device__ float    g_s[2432];       // s1[64] ss1[64] s2[128] ss2[128] s3[1024] ss3[1024]
__device__ __align__(16) float g_ab[384];  // a1[64] b1[64] a2[128] b2[128]
__device__ unsigned g_z3e[B_*1024];
__device__ float    g_g[B_*1024];
__device__ float    g_g4[B_*512];
__device__ float    g_mat[B_*9];
__device__ float    g_bias[B_*3];
__device__ int      g_c0 = 0;
__device__ int      g_c1 = 0;
__device__ int      g_c2 = 0;
// transposed weights for coalesced loads (R8 layouts)
__device__ ulonglong2 g_w2t[32][64];       // [j2][cp]
__device__ ulonglong2 g_w3t[8][32][128];   // [chunk][j2][t]

__device__ __forceinline__ float lrelu(float x){ return x >= 0.f ? x : 0.2f*x; }
__device__ __forceinline__ unsigned fenc(float f){
    unsigned u = __float_as_uint(f);
    return (u & 0x80000000u) ? ~u : (u | 0x80000000u);
}
__device__ __forceinline__ float fdec(unsigned u){
    u = (u & 0x80000000u) ? (u & 0x7FFFFFFFu) : ~u;
    return __uint_as_float(u);
}
__device__ __forceinline__ float f2lo(ull v){ return __uint_as_float((unsigned)v); }
__device__ __forceinline__ float f2hi(ull v){ return __uint_as_float((unsigned)(v>>32)); }
__device__ __forceinline__ void ffma2(ull& d, ull a, ull b){
    asm("fma.rn.f32x2 %0, %1, %2, %0;" : "+l"(d) : "l"(a), "l"(b));
}
__device__ __forceinline__ void fadd2(ull& d, ull b){
    asm("add.rn.f32x2 %0, %0, %1;" : "+l"(d) : "l"(b));
}

// ---------------- kernel 0: zero + SoA + norms + conv1 precompute + W transposes ----
__global__ void k_prep(const float* __restrict__ x, const float* __restrict__ w1,
                       const float* __restrict__ w2, const float* __restrict__ w3){
    __shared__ float wa[384], wd[384];
    int t = threadIdx.x;
    if (blockIdx.x == 0){
        for (int i = t; i < 2432; i += 256) g_s[i] = 0.f;
        for (int i = t; i < B_*1024; i += 256) g_z3e[i] = 0u;
    }
    for (int i = t; i < 384; i += 256){
        int o = i/6, c = i%6;
        float a = w1[o*12 + c];
        wa[i] = a;
        wd[i] = w1[o*12 + 6 + c] - a;
    }
    __syncthreads();

    int p = blockIdx.x*256 + t;            // 128 blocks x 256 = 32768
    // W3 transpose
    {
        int chunk = p >> 12;
        int rem   = p & 4095;
        int j2 = rem >> 7;
        int tt = rem & 127;
        int kh = tt & 1, p2 = tt >> 1;
        int row = chunk*128 + 2*p2 + (j2 >= 16 ? 1 : 0);
        int j = j2 & 15;
        g_w3t[chunk][j2][tt] = ((const ulonglong2*)(w3 + row*128 + kh*64))[j];
    }
    // W2 transpose
    if (p < 2048){
        int j2 = p >> 6, cp = p & 63;
        int row = 2*cp + (j2 >= 16 ? 1 : 0);
        int j = j2 & 15;
        g_w2t[j2][cp] = ((const ulonglong2*)(w2 + row*64))[j];
    }
    {
        int b = p >> 12, n = p & 4095;
        const float* xb = x + b*6*N_ + n;
        float x0=xb[0], x1=xb[N_], x2=xb[2*N_], x3=xb[3*N_], x4=xb[4*N_], x5=xb[5*N_];
        g_xp[p]       = make_float2(x0,x1);
        g_xp[PTS+p]   = make_float2(x2,x3);
        g_xp[2*PTS+p] = make_float2(x4,x5);
        g_xx[p] = x0*x0+x1*x1+x2*x2+x3*x3+x4*x4+x5*x5;
    }
    int o = t & 63;
    int pbase = blockIdx.x*256;
    for (int pi = (t>>6); pi < 256; pi += 4){
        int pp = pbase + pi;
        int bb = pp >> 12, nn = pp & 4095;
        const float* xp = x + bb*6*N_ + nn;
        float y0=xp[0], y1=xp[N_], y2=xp[2*N_], y3=xp[3*N_], y4=xp[4*N_], y5=xp[5*N_];
        const float* A = wa + o*6;
        const float* D = wd + o*6;
        g_nb[pp*64+o] = y0*A[0]+y1*A[1]+y2*A[2]+y3*A[3]+y4*A[4]+y5*A[5];
        g_cc[pp*64+o] = y0*D[0]+y1*D[1]+y2*D[2]+y3*D[3]+y4*D[4]+y5*D[5];
    }
}

// ---------------- kernel 1: KNN top-20 (4 queries/warp, short insert chain) -------
__global__ void __launch_bounds__(512) k_knn(){
    int b   = blockIdx.x >> 6;
    int sec = blockIdx.x & 63;
    int w    = threadIdx.x >> 5;
    int lane = threadIdx.x & 31;
    int base = b*N_;
    const float2* xp0 = g_xp + base;
    const float2* xp1 = g_xp + PTS + base;
    const float2* xp2 = g_xp + 2*PTS + base;
    const float*  xxp = g_xx + base;

    int n0 = sec*64 + w*4;
    float q[4][6]; float lv[4]; int li[4]; float minv[4];
    #pragma unroll
    for (int j=0;j<4;j++){
        float2 a = xp0[n0+j], c = xp1[n0+j], e = xp2[n0+j];
        q[j][0]=a.x; q[j][1]=a.y; q[j][2]=c.x; q[j][3]=c.y; q[j][4]=e.x; q[j][5]=e.y;
        lv[j] = -3.4e38f; li[j] = 0; minv[j] = -3.4e38f;
    }

    for (int mb = 0; mb < N_; mb += 32){
        int m = mb + lane;
        float2 a = xp0[m], c = xp1[m], e = xp2[m];
        float xxm = xxp[m];
        float v[4];
        #pragma unroll
        for (int j=0;j<4;j++){
            float d = q[j][0]*a.x + q[j][1]*a.y + q[j][2]*c.x
                    + q[j][3]*c.y + q[j][4]*e.x + q[j][5]*e.y;
            v[j] = 2.f*d - xxm;
        }
        #pragma unroll
        for (int j=0;j<4;j++){
            unsigned cand = __ballot_sync(FULLMASK, v[j] > minv[j]);
            bool any = (cand != 0u);
            while (cand){
                int src = __ffs(cand)-1; cand &= cand-1;
                float cv = __shfl_sync(FULLMASK, v[j], src);
                float pv = __shfl_up_sync(FULLMASK, lv[j], 1);
                int   pq = __shfl_up_sync(FULLMASK, li[j], 1);
                unsigned lt = __ballot_sync(FULLMASK, lv[j] < cv) & 0xFFFFFu;
                if (lt){
                    int pos = __ffs(lt)-1;
                    if (lane > pos && lane < KNN){ lv[j]=pv; li[j]=pq; }
                    if (lane == pos)             { lv[j]=cv; li[j]=mb+src; }
                }
            }
            if (any) minv[j] = __shfl_sync(FULLMASK, lv[j], 19);
        }
    }
    #pragma unroll
    for (int j=0;j<4;j++)
        if (lane < KNN) g_idx[(base + n0 + j)*KNN + lane] = li[j];
}

// ---------------- kernel 2: z1 channel stats + bn1 finalize (last block) ----------------
__global__ void __launch_bounds__(256) k_stats1(const float* __restrict__ ga,
                                                const float* __restrict__ be){
    int t = threadIdx.x, o = t & 63, grp = t >> 6;
    float s = 0.f, ss = 0.f;
    for (int pi = blockIdx.x*4 + grp; pi < PTS; pi += 4096){
        float ccv = g_cc[pi*64 + o];
        int bbase = (pi >> 12) << 12;
        const int* ip = g_idx + pi*KNN;
        #pragma unroll
        for (int k=0;k<KNN;k++){
            int r = ip[k];
            float v = g_nb[(bbase + r)*64 + o] + ccv;
            s += v; ss += v*v;
        }
    }
    __shared__ float sh[256], sh2[256];
    sh[t] = s; sh2[t] = ss;
    __syncthreads();
    if (t < 64){
        atomicAdd(&g_s[t],    sh[t]+sh[t+64]+sh[t+128]+sh[t+192]);
        atomicAdd(&g_s[64+t], sh2[t]+sh2[t+64]+sh2[t+128]+sh2[t+192]);
    }
    __threadfence();
    __syncthreads();
    __shared__ int lastb;
    if (t == 0) lastb = (atomicAdd(&g_c0, 1) == (int)gridDim.x - 1);
    __syncthreads();
    if (lastb){
        if (t < 64){
            float cnt = (float)(PTS*KNN);
            float m = g_s[t]/cnt;
            float var = g_s[64+t]/cnt - m*m;
            float a = ga[t]*rsqrtf(var + 1e-5f);
            g_ab[t]    = a;
            g_ab[64+t] = be[t] - m*a;
        }
        if (t == 0) g_c0 = 0;
    }
}

// ---------------- kernel 3: conv2, vectorized gather (LDG.128/STS.128) ------------
// grid 444 persistent, 128 threads.
// Gather role: rid=t>>4 (rows rid,rid+8,..,rid+72), c16=t&15 (channels c16*4..+3).
// Compute role: kh=t>>6, cp=t&63 (channels 2cp,2cp+1) — R8 structure.
#define C2_TILES 2048
__global__ void __launch_bounds__(128) k_conv2(const float* __restrict__ ga,
                                               const float* __restrict__ be){
    int t = threadIdx.x;
    int kh = t >> 6;
    int cp = t & 63;
    int rid = t >> 4, c16 = t & 15;
    ull w0[32], w1[32];
    #pragma unroll
    for (int j=0;j<16;j++){
        ulonglong2 v0 = g_w2t[j][cp];    w0[2*j]=v0.x; w0[2*j+1]=v0.y;
        ulonglong2 v1 = g_w2t[16+j][cp]; w1[2*j]=v1.x; w1[2*j+1]=v1.y;
    }
    float4 a4 = *(const float4*)(g_ab + c16*4);
    float4 b4 = *(const float4*)(g_ab + 64 + c16*4);
    __shared__ __align__(16) float h1[4][20*64];
    __shared__ float mx[2][4][128];
    float s0=0.f, ss0=0.f, s1=0.f, ss1=0.f;

    for (int tile = blockIdx.x; tile < C2_TILES; tile += gridDim.x){
        int p0 = tile*16;
        int bbase = (p0 >> 12) << 12;     // 16-pt tiles never cross batch boundary
        for (int ph = 0; ph < 4; ++ph){
            int pb = p0 + ph*4;
            __syncthreads();
            if (ph > 0 && kh == 0){
                #pragma unroll
                for (int pp=0;pp<4;pp++){
                    int pi = pb - 4 + pp;
                    float2 v;
                    v.x = fmaxf(mx[0][pp][2*cp],   mx[1][pp][2*cp]);
                    v.y = fmaxf(mx[0][pp][2*cp+1], mx[1][pp][2*cp+1]);
                    *(float2*)(g_m2 + pi*128 + 2*cp) = v;
                }
            }
            // ---- vectorized gather: 80 rows x 16 float4-slots ----
            float4 cc4[4];
            #pragma unroll
            for (int pp=0;pp<4;pp++)
                cc4[pp] = *(const float4*)(g_cc + (pb+pp)*64 + c16*4);
            #pragma unroll
            for (int i=0;i<10;i++){
                int rr = rid + i*8;           // 0..79
                int pp = rr / KNN, k = rr % KNN;
                int r = __ldg(&g_idx[(pb+pp)*KNN + k]);
                float4 v = *(const float4*)(g_nb + ((bbase + r)<<6) + c16*4);
                float4 cv = cc4[pp];
                float4 z;
                z.x = lrelu(fmaf(a4.x, v.x + cv.x, b4.x));
                z.y = lrelu(fmaf(a4.y, v.y + cv.y, b4.y));
                z.z = lrelu(fmaf(a4.z, v.z + cv.z, b4.z));
                z.w = lrelu(fmaf(a4.w, v.w + cv.w, b4.w));
                *(float4*)(h1[pp] + k*64 + c16*4) = z;
            }
            __syncthreads();
            // ---- compute 4 points x 10 k (per k-half role) ----
            #pragma unroll
            for (int pp=0;pp<4;pp++){
                float m0 = -3.4e38f, m1 = -3.4e38f;
                for (int kk=0;kk<10;kk++){
                    int k = kh*10 + kk;
                    const ulonglong2* hp = (const ulonglong2*)(h1[pp] + k*64);
                    ull A0=0ull, B0=0ull, A1=0ull, B1=0ull;
                    #pragma unroll
                    for (int j=0;j<16;j++){
                        ulonglong2 h = hp[j];
                        ffma2(A0, w0[2*j],   h.x);
                        ffma2(B0, w0[2*j+1], h.y);
                        ffma2(A1, w1[2*j],   h.x);
                        ffma2(B1, w1[2*j+1], h.y);
                    }
                    fadd2(A0, B0); fadd2(A1, B1);
                    float z0 = f2lo(A0) + f2hi(A0);
                    float z1 = f2lo(A1) + f2hi(A1);
                    s0 += z0; ss0 += z0*z0; m0 = fmaxf(m0, z0);
                    s1 += z1; ss1 += z1*z1; m1 = fmaxf(m1, z1);
                }
                mx[kh][pp][2*cp]   = m0;
                mx[kh][pp][2*cp+1] = m1;
            }
        }
        __syncthreads();
        if (kh == 0){
            #pragma unroll
            for (int pp=0;pp<4;pp++){
                int pi = p0 + 12 + pp;
                float2 v;
                v.x = fmaxf(mx[0][pp][2*cp],   mx[1][pp][2*cp]);
                v.y = fmaxf(mx[0][pp][2*cp+1], mx[1][pp][2*cp+1]);
                *(float2*)(g_m2 + pi*128 + 2*cp) = v;
            }
        }
    }
    atomicAdd(&g_s[128+2*cp],   s0);
    atomicAdd(&g_s[128+2*cp+1], s1);
    atomicAdd(&g_s[256+2*cp],   ss0);
    atomicAdd(&g_s[256+2*cp+1], ss1);
    __threadfence();
    __syncthreads();
    __shared__ int lastb;
    if (t == 0) lastb = (atomicAdd(&g_c1, 1) == (int)gridDim.x - 1);
    __syncthreads();
    if (lastb){
        float cnt = (float)(PTS*KNN);
        float m = g_s[128+t]/cnt;
        float var = g_s[256+t]/cnt - m*m;
        float a = ga[t]*rsqrtf(var + 1e-5f);
        g_ab[128+t] = a;
        g_ab[256+t] = be[t] - m*a;
        if (t == 0) g_c1 = 0;
    }
}

// ---------------- kernel 4: conv3 with cp.async streaming double-buffer ------------
#define C3_UNITS 2048
__global__ void __launch_bounds__(128) k_conv3(const float* __restrict__ ga,
                                               const float* __restrict__ be){
    int t = threadIdx.x;
    int kh = t & 1;
    __shared__ __align__(16) float h2[2][16*128];   // 16KB double buffer
    __shared__ float sab[128], sbb[128];
    sab[t] = g_ab[128+t]; sbb[t] = g_ab[256+t];
    float a2 = g_ab[128+t], b2 = g_ab[256+t];
    __syncthreads();

    for (int u = blockIdx.x; u < C3_UNITS; u += gridDim.x){
        int chunk = u & 7;
        int bb    = (u >> 3) & 7;
        int sec   = u >> 6;            // 0..31
        ull w0[32], w1[32];
        #pragma unroll
        for (int j=0;j<16;j++){
            ulonglong2 v0 = g_w3t[chunk][j][t];    w0[2*j]=v0.x; w0[2*j+1]=v0.y;
            ulonglong2 v1 = g_w3t[chunk][16+j][t]; w1[2*j]=v1.x; w1[2*j+1]=v1.y;
        }
        float s=0.f, ss=0.f, maxv=-3.4e38f;
        int pbase = (bb << 12) + sec*128;
        const float4* src0 = (const float4*)(g_m2 + (size_t)pbase*128);

        #pragma unroll
        for (int k4=0;k4<4;k4++){
            int i = t + 128*k4;
            unsigned dst = (unsigned)__cvta_generic_to_shared(&((float4*)h2[0])[i]);
            asm volatile("cp.async.ca.shared.global [%0], [%1], 16;\n"
                         :: "r"(dst), "l"(src0 + i));
        }
        asm volatile("cp.async.commit_group;\n");

        for (int ph = 0; ph < 8; ++ph){
            int par = ph & 1;
            asm volatile("cp.async.wait_group 0;\n");
            __syncthreads();
            #pragma unroll
            for (int k16=0;k16<16;k16++){
                float v = h2[par][k16*128 + t];
                h2[par][k16*128 + t] = lrelu(fmaf(a2, v, b2));
            }
            __syncthreads();
            if (ph < 7){
                const float4* srcn = (const float4*)(g_m2 + (size_t)(pbase + (ph+1)*16)*128);
                #pragma unroll
                for (int k4=0;k4<4;k4++){
                    int i = t + 128*k4;
                    unsigned dst = (unsigned)__cvta_generic_to_shared(&((float4*)h2[1-par])[i]);
                    asm volatile("cp.async.ca.shared.global [%0], [%1], 16;\n"
                                 :: "r"(dst), "l"(srcn + i));
                }
                asm volatile("cp.async.commit_group;\n");
            }
            #pragma unroll 2
            for (int pl=0; pl<16; ++pl){
                const ulonglong2* hp = (const ulonglong2*)(h2[par] + pl*128 + kh*64);
                ull A0=0ull, B0=0ull, A1=0ull, B1=0ull;
                #pragma unroll
                for (int j=0;j<16;j++){
                    ulonglong2 h = hp[j];
                    ffma2(A0, w0[2*j],   h.x);
                    ffma2(B0, w0[2*j+1], h.y);
                    ffma2(A1, w1[2*j],   h.x);
                    ffma2(B1, w1[2*j+1], h.y);
                }
                fadd2(A0, B0); fadd2(A1, B1);
                float z0p = f2lo(A0) + f2hi(A0);
                float z1p = f2lo(A1) + f2hi(A1);
                float z0 = z0p + __shfl_xor_sync(FULLMASK, z0p, 1);
                float z1 = z1p + __shfl_xor_sync(FULLMASK, z1p, 1);
                float z = kh ? z1 : z0;
                s += z; ss += z*z;
                maxv = fmaxf(maxv, z);
            }
        }
        int ch = chunk*128 + t;
        atomicAdd(&g_s[384+ch],  s);
        atomicAdd(&g_s[1408+ch], ss);
        atomicMax(&g_z3e[bb*1024 + ch], fenc(maxv));
        __syncthreads();
    }
    __threadfence();
    __syncthreads();
    __shared__ int lastb;
    if (t == 0) lastb = (atomicAdd(&g_c2, 1) == (int)gridDim.x - 1);
    __syncthreads();
    if (lastb){
        float cnt = (float)PTS;
        for (int c = t; c < 1024; c += 128){
            float m = g_s[384+c]/cnt;
            float var = g_s[1408+c]/cnt - m*m;
            float a = ga[c]*rsqrtf(var + 1e-5f);
            float bo = be[c] - m*a;
            #pragma unroll
            for (int b=0;b<B_;b++)
                g_g[b*1024+c] = lrelu(fmaf(a, fdec(g_z3e[b*1024+c]), bo));
        }
        if (t == 0) g_c2 = 0;
    }
}

// ---------------- kernel 5: fc1 + bn4 + lrelu ----------------
__global__ void __launch_bounds__(128) k_fc1(const float* __restrict__ fw,
                                             const float* __restrict__ g4g,
                                             const float* __restrict__ g4b){
    __shared__ float gs[B_*1024];
    int t = threadIdx.x;
    for (int i=t;i<B_*1024;i+=128) gs[i] = g_g[i];
    __syncthreads();
    int w = t >> 5, lane = t & 31;
    for (int jj=0;jj<2;jj++){
        int j = blockIdx.x*8 + w*2 + jj;
        const float* wrow = fw + j*1024;
        float acc[8] = {0,0,0,0,0,0,0,0};
        for (int c=lane;c<1024;c+=32){
            float wv = wrow[c];
            #pragma unroll
            for (int b=0;b<8;b++) acc[b] += gs[b*1024+c]*wv;
        }
        #pragma unroll
        for (int b=0;b<8;b++){
            #pragma unroll
            for (int off=16;off;off>>=1) acc[b] += __shfl_xor_sync(FULLMASK, acc[b], off);
        }
        if (lane == 0){
            float m=0.f;
            #pragma unroll
            for (int b=0;b<8;b++) m += acc[b];
            m *= 0.125f;
            float var=0.f;
            #pragma unroll
            for (int b=0;b<8;b++){ float d = acc[b]-m; var += d*d; }
            var *= 0.125f;
            float a = g4g[j]*rsqrtf(var + 1e-5f);
            float bo = g4b[j] - m*a;
            #pragma unroll
            for (int b=0;b<8;b++) g_g4[b*512+j] = lrelu(a*acc[b] + bo);
        }
    }
}

// ---------------- kernel 6: fc2+bn5+lrelu, fc3/fc4 -> mat/bias ----------------
__global__ void __launch_bounds__(256) k_head(const float* __restrict__ f2w,
        const float* __restrict__ g5g, const float* __restrict__ g5b,
        const float* __restrict__ f3w, const float* __restrict__ f3b,
        const float* __restrict__ f4w, const float* __restrict__ f4b){
    __shared__ float g4s[B_*512];
    __shared__ float g5s[B_*256];
    int t = threadIdx.x, w = t >> 5, lane = t & 31;
    for (int i=t;i<B_*512;i+=256) g4s[i] = g_g4[i];
    __syncthreads();
    for (int jj=0;jj<32;jj++){
        int j = w*32 + jj;
        const float* wrow = f2w + j*512;
        float acc[8] = {0,0,0,0,0,0,0,0};
        for (int c=lane;c<512;c+=32){
            float wv = wrow[c];
            #pragma unroll
            for (int b=0;b<8;b++) acc[b] += g4s[b*512+c]*wv;
        }
        #pragma unroll
        for (int b=0;b<8;b++){
            #pragma unroll
            for (int off=16;off;off>>=1) acc[b] += __shfl_xor_sync(FULLMASK, acc[b], off);
        }
        if (lane == 0){
            float m=0.f;
            #pragma unroll
            for (int b=0;b<8;b++) m += acc[b];
            m *= 0.125f;
            float var=0.f;
            #pragma unroll
            for (int b=0;b<8;b++){ float d = acc[b]-m; var += d*d; }
            var *= 0.125f;
            float a = g5g[j]*rsqrtf(var + 1e-5f);
            float bo = g5b[j] - m*a;
            #pragma unroll
            for (int b=0;b<8;b++) g5s[b*256+j] = lrelu(a*acc[b] + bo);
        }
    }
    __syncthreads();
    for (int i=0;i<12;i++){
        int task = w*12 + i;
        int b = task / 12, jo = task % 12;
        const float* wrow = (jo < 9) ? (f3w + jo*256) : (f4w + (jo-9)*256);
        float acc = 0.f;
        for (int c=lane;c<256;c+=32) acc += g5s[b*256+c]*wrow[c];
        #pragma unroll
        for (int off=16;off;off>>=1) acc += __shfl_xor_sync(FULLMASK, acc, off);
        if (lane == 0){
            if (jo < 9){
                int r = jo/3, cc = jo%3;
                g_mat[b*9+jo] = acc + f3b[jo] + (r==cc ? 1.f : 0.f);
            } else {
                g_bias[b*3 + (jo-9)] = acc + f4b[jo-9];
            }
        }
    }
}

// ---------------- kernel 7: apply 3x3 transform ----------------
__global__ void k_out(const float* __restrict__ x, float* __restrict__ out){
    int p = blockIdx.x*1024 + threadIdx.x;
    int b = p >> 12, n = p & 4095;
    const float* xb = x + b*6*N_ + n;
    float x0 = xb[0], x1 = xb[N_], x2 = xb[2*N_];
    const float* M  = g_mat + b*9;
    const float* Bi = g_bias + b*3;
    float* ob = out + b*3*N_ + n;
    ob[0]    = x0*M[0] + x1*M[3] + x2*M[6] + Bi[0];
    ob[N_]   = x0*M[1] + x1*M[4] + x2*M[7] + Bi[1];
    ob[2*N_] = x0*M[2] + x1*M[5] + x2*M[8] + Bi[2];
}

// ---------------- launch ----------------
extern "C" void kernel_launch(void* const* d_in, const int* in_sizes, int n_in,
                              void* d_out, int out_size){
    const float* x     = (const float*)d_in[0];
    const float* w1    = (const float*)d_in[1];
    const float* bn1g  = (const float*)d_in[2];
    const float* bn1b  = (const float*)d_in[3];
    const float* w2    = (const float*)d_in[4];
    const float* bn2g  = (const float*)d_in[5];
    const float* bn2b  = (const float*)d_in[6];
    const float* w3    = (const float*)d_in[7];
    const float* bn3g  = (const float*)d_in[8];
    const float* bn3b  = (const float*)d_in[9];
    const float* fc1w  = (const float*)d_in[10];
    const float* bn4g  = (const float*)d_in[11];
    const float* bn4b  = (const float*)d_in[12];
    const float* fc2w  = (const float*)d_in[13];
    const float* bn5g  = (const float*)d_in[14];
    const float* bn5b  = (const float*)d_in[15];
    const float* fc3w  = (const float*)d_in[16];
    const float* fc3b  = (const float*)d_in[17];
    const float* fc4w  = (const float*)d_in[18];
    const float* fc4b  = (const float*)d_in[19];
    float* out = (float*)d_out;

    k_prep  <<<128, 256>>>(x, w1, w2, w3);  // 1
    k_knn   <<<B_*64, 512>>>();             // 2
    k_stats1<<<1024, 256>>>(bn1g, bn1b);    // 3
    k_conv2 <<<444, 128>>>(bn2g, bn2b);     // 4  <- ncu capture slot
    k_conv3 <<<444, 128>>>(bn3g, bn3b);     // 5
    k_fc1   <<<64, 128>>>(fc1w, bn4g, bn4b);
    k_head  <<<1, 256>>>(fc2w, bn5g, bn5b, fc3w, fc3b, fc4w, fc4b);
    k_out   <<<32, 1024>>>(x, out);
}